// round 10
// baseline (speedup 1.0000x reference)
#include <cuda_runtime.h>

#define Bn 4
#define Cn 64
#define Hn 128
#define Wn 128
#define HWn (Hn*Wn)

// ---------------- scratch (device globals; no runtime allocation) ----------------
__device__ __align__(16) float g_xT[Bn*HWn*Cn];       // x  in [B,H,W,C]
__device__ __align__(16) float g_interT[Bn*HWn*Cn];   // inter in [B,H,W,C]
__device__ __align__(16) float g_om[Bn*HWn*32];       // offsets+mask, pixel-major, pad 32
__device__ __align__(16) float g_woffT[1152*32];      // [r=cin*9+tap][o(pad32)]
__device__ __align__(16) float g_wdcnT[576*64];       // [r=c*9+k][o]
__device__ __align__(16) float g_wg1T[4096];          // [c][o]
__device__ __align__(16) float g_wg2T[4096];
__device__ __align__(16) float g_wb1T[4096];
__device__ __align__(16) float g_wb2T[4096];

// ---------------- weight prep ----------------
__global__ void prep_weights(const float* __restrict__ w_off,
                             const float* __restrict__ w_dcn,
                             const float* __restrict__ wg1, const float* __restrict__ wg2,
                             const float* __restrict__ wb1, const float* __restrict__ wb2) {
    int idx = blockIdx.x * blockDim.x + threadIdx.x;
    if (idx < 1152*32) {
        int r = idx >> 5, o = idx & 31;
        g_woffT[idx] = (o < 27) ? w_off[o*1152 + r] : 0.f;
    }
    if (idx < 576*64) {
        int r = idx >> 6, o = idx & 63;
        g_wdcnT[idx] = w_dcn[o*576 + r];
    }
    if (idx < 4096) {
        int c = idx >> 6, o = idx & 63;
        g_wg1T[idx] = wg1[o*64 + c];
        g_wg2T[idx] = wg2[o*64 + c];
        g_wb1T[idx] = wb1[o*64 + c];
        g_wb2T[idx] = wb2[o*64 + c];
    }
}

// ---------------- NCHW -> NHWC transpose ----------------
__global__ void transpose_k(const float* __restrict__ in, int which) {
    __shared__ float tile[32][33];
    float* out = which ? g_interT : g_xT;
    int b = blockIdx.z;
    int n0 = blockIdx.x * 32;
    int c0 = blockIdx.y * 32;
    int tx = threadIdx.x, ty = threadIdx.y;
    const float* src = in + (size_t)b * Cn * HWn;
    float* dst = out + (size_t)b * HWn * Cn;
#pragma unroll
    for (int i = 0; i < 32; i += 8)
        tile[ty + i][tx] = src[(size_t)(c0 + ty + i) * HWn + n0 + tx];
    __syncthreads();
#pragma unroll
    for (int i = 0; i < 32; i += 8)
        dst[(size_t)(n0 + ty + i) * Cn + c0 + tx] = tile[tx][ty + i];
}

// ---------------- offset conv ----------------
// block: 256 thr = 8 o-groups(4 out) x 32 lanes(2 px each) -> 64 pixels x 32 outputs
// staged in 32-channel chunks: smem 32ch x 3rows x 66cols = 25344 B (static)
__global__ __launch_bounds__(256) void offset_conv_k(
    const float* __restrict__ x, const float* __restrict__ inter,
    const float* __restrict__ b_off) {
    __shared__ __align__(16) float s_in[32 * 198];   // [ci][ry(3)][cx(66)]
    int b = blockIdx.z, h = blockIdx.y, w0 = blockIdx.x * 64;
    int tid = threadIdx.x;
    int og = tid >> 5, lane = tid & 31;
    int o0 = og * 4, p0 = lane * 2;
    float acc0[4] = {0.f,0.f,0.f,0.f};   // pixel p0
    float acc1[4] = {0.f,0.f,0.f,0.f};   // pixel p0+1

    for (int half = 0; half < 2; ++half) {
        const float* src = half ? inter : x;
        for (int chunk = 0; chunk < 2; ++chunk) {
            int cbase = chunk * 32;
            __syncthreads();
            for (int idx = tid; idx < 32 * 198; idx += 256) {
                int ci = idx / 198; int rem = idx - ci * 198;
                int ry = rem / 66;  int cx = rem - ry * 66;
                int y = h - 1 + ry, xw = w0 - 1 + cx;
                float v = 0.f;
                if ((unsigned)y < (unsigned)Hn && (unsigned)xw < (unsigned)Wn)
                    v = src[((size_t)(b * Cn + cbase + ci) * Hn + y) * Wn + xw];
                s_in[idx] = v;
            }
            __syncthreads();
            const float* wb = g_woffT + (half * 64 + cbase) * 288 + o0;
            for (int ci = 0; ci < 32; ++ci) {
                const float* srow = s_in + ci * 198 + p0;
                // 3x4 input patch for this thread's 2 pixels (6 x LDS.64)
                float v[3][4];
#pragma unroll
                for (int ry = 0; ry < 3; ++ry) {
                    float2 u0 = *(const float2*)(srow + ry * 66);
                    float2 u1 = *(const float2*)(srow + ry * 66 + 2);
                    v[ry][0] = u0.x; v[ry][1] = u0.y;
                    v[ry][2] = u1.x; v[ry][3] = u1.y;
                }
                const float* wr = wb + ci * 288;
#pragma unroll
                for (int tap = 0; tap < 9; ++tap) {
                    float4 w4 = *(const float4*)(wr + tap * 32);
                    int ry = tap / 3, kx = tap - ry * 3;
                    float s0 = v[ry][kx];
                    float s1 = v[ry][kx + 1];
                    acc0[0] += w4.x * s0; acc0[1] += w4.y * s0;
                    acc0[2] += w4.z * s0; acc0[3] += w4.w * s0;
                    acc1[0] += w4.x * s1; acc1[1] += w4.y * s1;
                    acc1[2] += w4.z * s1; acc1[3] += w4.w * s1;
                }
            }
        }
    }

    float bj[4];
#pragma unroll
    for (int j = 0; j < 4; ++j) bj[j] = (o0 + j < 27) ? b_off[o0 + j] : 0.f;

    size_t pixbase = ((size_t)b * Hn + h) * Wn + w0;
#pragma unroll
    for (int px = 0; px < 2; ++px) {
        float* a = px ? acc1 : acc0;
        float4 r;
        float* rv = (float*)&r;
#pragma unroll
        for (int j = 0; j < 4; ++j) {
            int o = o0 + j;
            float vv = a[j] + bj[j];
            if (o >= 18 && o < 27) vv = 1.f / (1.f + expf(-vv));
            rv[j] = vv;
        }
        *(float4*)(g_om + (pixbase + p0 + px) * 32 + o0) = r;
    }
}

__device__ __forceinline__ float lrelu(float v) { return v >= 0.f ? v : 0.1f * v; }

// ---------------- fused: SFT chains + deformable sampling + DCN + residual ----
// block covers 32 pixels. 256 thr = 16 o-groups(4 out) x 16 t(2 px each: 2t, 2t+1)
// dynamic smem: s_samp [576][34] + s_om [32][27]  = 81792 B
__global__ __launch_bounds__(256) void fused_k(float* __restrict__ out) {
    extern __shared__ __align__(16) float smem[];
    float* s_samp = smem;                  // [576][34]
    float* s_om   = smem + 576 * 34;       // [32][27]
    // aliased into s_samp (dead before sampling writes it):
    float* s_iv = smem;                    // [32][65]
    float* s_t1 = smem + 2080;             // [32][67]
    float* s_t2 = smem + 2080 + 2144;      // [32][67]

    int b = blockIdx.z, h = blockIdx.y, w0 = blockIdx.x * 32;
    int tid = threadIdx.x;
    int og = tid >> 4, t = tid & 15, o0 = og * 4;
    int px0 = 2 * t, px1 = 2 * t + 1;
    size_t pixbase = ((size_t)b * Hn + h) * Wn + w0;

    // load om (27/px) and inter vectors (64/px)
    for (int idx = tid; idx < 32 * 27; idx += 256) {
        int pp = idx / 27, c = idx - pp * 27;
        s_om[idx] = g_om[(pixbase + pp) * 32 + c];
    }
    for (int idx = tid; idx < 32 * 64; idx += 256) {
        int pp = idx >> 6, c = idx & 63;
        s_iv[pp * 65 + c] = g_interT[(pixbase + pp) * 64 + c];
    }
    __syncthreads();

    // stage 1: t1 = lrelu(w_g1 @ iv), t2 = lrelu(w_b1 @ iv)   (2 pixels/thread)
    float a1[2][4] = {{0}}, a2[2][4] = {{0}};
#pragma unroll 4
    for (int c = 0; c < 64; ++c) {
        float v0 = s_iv[px0 * 65 + c];
        float v1 = s_iv[px1 * 65 + c];
        float4 w1 = *(const float4*)(g_wg1T + c * 64 + o0);
        float4 w2 = *(const float4*)(g_wb1T + c * 64 + o0);
        a1[0][0] += w1.x * v0; a1[0][1] += w1.y * v0; a1[0][2] += w1.z * v0; a1[0][3] += w1.w * v0;
        a1[1][0] += w1.x * v1; a1[1][1] += w1.y * v1; a1[1][2] += w1.z * v1; a1[1][3] += w1.w * v1;
        a2[0][0] += w2.x * v0; a2[0][1] += w2.y * v0; a2[0][2] += w2.z * v0; a2[0][3] += w2.w * v0;
        a2[1][0] += w2.x * v1; a2[1][1] += w2.y * v1; a2[1][2] += w2.z * v1; a2[1][3] += w2.w * v1;
    }
#pragma unroll
    for (int px = 0; px < 2; ++px) {
        float* t1p = s_t1 + (2 * t + px) * 67 + o0;
        float* t2p = s_t2 + (2 * t + px) * 67 + o0;
#pragma unroll
        for (int j = 0; j < 4; ++j) { t1p[j] = lrelu(a1[px][j]); t2p[j] = lrelu(a2[px][j]); }
    }
    __syncthreads();

    // stage 2: gamma = w_g2 @ t1, beta = w_b2 @ t2 (kept in regs)
    float gm[2][4] = {{0}}, bt[2][4] = {{0}};
#pragma unroll 4
    for (int c = 0; c < 64; ++c) {
        float u0 = s_t1[px0 * 67 + c];
        float u1 = s_t1[px1 * 67 + c];
        float v0 = s_t2[px0 * 67 + c];
        float v1 = s_t2[px1 * 67 + c];
        float4 w1 = *(const float4*)(g_wg2T + c * 64 + o0);
        float4 w2 = *(const float4*)(g_wb2T + c * 64 + o0);
        gm[0][0] += w1.x * u0; gm[0][1] += w1.y * u0; gm[0][2] += w1.z * u0; gm[0][3] += w1.w * u0;
        gm[1][0] += w1.x * u1; gm[1][1] += w1.y * u1; gm[1][2] += w1.z * u1; gm[1][3] += w1.w * u1;
        bt[0][0] += w2.x * v0; bt[0][1] += w2.y * v0; bt[0][2] += w2.z * v0; bt[0][3] += w2.w * v0;
        bt[1][0] += w2.x * v1; bt[1][1] += w2.y * v1; bt[1][2] += w2.z * v1; bt[1][3] += w2.w * v1;
    }
    __syncthreads();   // aliased region reads done before sampling overwrites

    // sampling: s_samp[(c*9+k)*34 + pp] = bilinear(x, pp, k) * mask
    int wi = tid >> 5, lane = tid & 31;
    for (int task = wi; task < 32 * 9; task += 8) {
        int pp = task / 9, k = task - pp * 9;
        float dy = s_om[pp * 27 + k];
        float dx = s_om[pp * 27 + 9 + k];
        float m  = s_om[pp * 27 + 18 + k];
        int ky = k / 3, kx = k - ky * 3;
        float py = (float)(h + ky - 1) + dy;
        float pxc = (float)(w0 + pp + kx - 1) + dx;
        float fy = floorf(py), fx = floorf(pxc);
        float wy = py - fy, wx = pxc - fx;
        int y0 = (int)fy, x0 = (int)fx;
        bool vy0 = (unsigned)y0 < (unsigned)Hn;
        bool vy1 = (unsigned)(y0 + 1) < (unsigned)Hn;
        bool vx0 = (unsigned)x0 < (unsigned)Wn;
        bool vx1 = (unsigned)(x0 + 1) < (unsigned)Wn;
        float w00 = (1.f - wy) * (1.f - wx) * m;
        float w01 = (1.f - wy) * wx * m;
        float w10 = wy * (1.f - wx) * m;
        float w11 = wy * wx * m;
        const float* xb = g_xT + (size_t)b * HWn * Cn
                          + ((long long)y0 * Wn + x0) * Cn;
#pragma unroll
        for (int cc = 0; cc < 2; ++cc) {
            int c = lane + cc * 32;
            float v00 = (vy0 && vx0) ? xb[c] : 0.f;
            float v01 = (vy0 && vx1) ? xb[c + Cn] : 0.f;
            float v10 = (vy1 && vx0) ? xb[c + Wn * Cn] : 0.f;
            float v11 = (vy1 && vx1) ? xb[c + Wn * Cn + Cn] : 0.f;
            float val = v00 * w00 + v01 * w01 + v10 * w10 + v11 * w11;
            s_samp[(c * 9 + k) * 34 + pp] = val;
        }
    }
    __syncthreads();

    // DCN: d[px][o] = sum_r wdcnT[r][o] * samp[r][px]   (LDS.64 pixel pair)
    float d[2][4] = {{0}};
#pragma unroll 4
    for (int r = 0; r < 576; ++r) {
        float4 w4 = *(const float4*)(g_wdcnT + r * 64 + o0);
        float2 sp = *(const float2*)(s_samp + r * 34 + px0);
        d[0][0] += w4.x * sp.x; d[0][1] += w4.y * sp.x; d[0][2] += w4.z * sp.x; d[0][3] += w4.w * sp.x;
        d[1][0] += w4.x * sp.y; d[1][1] += w4.y * sp.y; d[1][2] += w4.z * sp.y; d[1][3] += w4.w * sp.y;
    }

    // epilogue: out = x + dcn + x*gamma + beta   (NCHW, float2 across pixel pair)
    float4 xv0 = *(const float4*)(g_xT + (pixbase + px0) * 64 + o0);
    float4 xv1 = *(const float4*)(g_xT + (pixbase + px1) * 64 + o0);
    const float* xa0 = (const float*)&xv0;
    const float* xa1 = (const float*)&xv1;
#pragma unroll
    for (int j = 0; j < 4; ++j) {
        float2 rr;
        rr.x = xa0[j] + d[0][j] + xa0[j] * gm[0][j] + bt[0][j];
        rr.y = xa1[j] + d[1][j] + xa1[j] * gm[1][j] + bt[1][j];
        *(float2*)(out + ((size_t)(b * Cn + o0 + j) * Hn + h) * Wn + w0 + px0) = rr;
    }
}

// ---------------- launch ----------------
extern "C" void kernel_launch(void* const* d_in, const int* in_sizes, int n_in,
                              void* d_out, int out_size) {
    const float* x     = (const float*)d_in[0];
    const float* inter = (const float*)d_in[1];
    const float* w_off = (const float*)d_in[2];
    const float* b_off = (const float*)d_in[3];
    const float* w_dcn = (const float*)d_in[4];
    const float* wg1   = (const float*)d_in[5];
    const float* wg2   = (const float*)d_in[6];
    const float* wb1   = (const float*)d_in[7];
    const float* wb2   = (const float*)d_in[8];
    float* out = (float*)d_out;

    const int fused_smem = (576 * 34 + 32 * 27) * 4;   // 81792 B
    static int attr_done = 0;
    if (!attr_done) {
        cudaFuncSetAttribute(fused_k, cudaFuncAttributeMaxDynamicSharedMemorySize, fused_smem);
        attr_done = 1;
    }

    prep_weights<<<144, 256>>>(w_off, w_dcn, wg1, wg2, wb1, wb2);
    transpose_k<<<dim3(HWn / 32, Cn / 32, Bn), dim3(32, 8)>>>(x, 0);
    transpose_k<<<dim3(HWn / 32, Cn / 32, Bn), dim3(32, 8)>>>(inter, 1);
    offset_conv_k<<<dim3(Wn / 64, Hn, Bn), 256>>>(x, inter, b_off);
    fused_k<<<dim3(Wn / 32, Hn, Bn), 256, fused_smem>>>(out);
}